// round 1
// baseline (speedup 1.0000x reference)
#include <cuda_runtime.h>
#include <cstdint>

#define BB 4
#define TT 4096
#define EE 2048
#define DD 128
#define KTOP 409
#define NKV_SLICES 8

// ---------------- scratch (device globals; no allocation allowed) ----------------
__device__ float g_q[(size_t)BB * TT * DD];          // 8 MB
__device__ float g_norm[BB * TT];                    // squared norms
__device__ int   g_topidx[BB * KTOP];
__device__ float g_qtop[BB * KTOP * DD];
__device__ float g_ktop[BB * KTOP * DD];
__device__ float g_vtop[BB * KTOP * DD];
__device__ float g_part[(size_t)NKV_SLICES * 2 * BB * KTOP * DD];  // split-K partials

// ---------------- packed fp32x2 helpers (sm_103a) ----------------
__device__ __forceinline__ void fma2(unsigned long long& d, unsigned long long a,
                                     unsigned long long b) {
    asm("fma.rn.f32x2 %0, %1, %2, %0;" : "+l"(d) : "l"(a), "l"(b));
}
__device__ __forceinline__ unsigned long long dup2(float x) {
    unsigned long long r;
    unsigned u = __float_as_uint(x);
    asm("mov.b64 %0, {%1, %1};" : "=l"(r) : "r"(u));
    return r;
}
__device__ __forceinline__ float2 unpk(unsigned long long u) {
    float2 f;
    asm("mov.b64 {%0, %1}, %2;" : "=f"(f.x), "=f"(f.y) : "l"(u));
    return f;
}

// ---------------- zero output ----------------
__global__ void zero_kernel(float4* o, int n4) {
    for (int i = blockIdx.x * blockDim.x + threadIdx.x; i < n4;
         i += gridDim.x * blockDim.x)
        o[i] = make_float4(0.f, 0.f, 0.f, 0.f);
}

// ---------------- 128x128 fp32 GEMM (A[*,2048] @ W[2048,128]) ----------------
// GATHER=false: full q GEMM (grid.x = 128 row tiles), writes g_q + g_norm.
// GATHER=true : gathered rows via g_topidx, grid = (16 tiles, 2 mats, 8 k-slices),
//               writes split-K partials to g_part.
template <bool GATHER>
__global__ __launch_bounds__(256) void sgemm128(const float* __restrict__ A,
                                                const float* __restrict__ W0,
                                                const float* __restrict__ W1) {
    __shared__ float As[2][8][128];
    __shared__ float Bs[2][8][128];
    const int tid = threadIdx.x;

    int tile, b = 0, kbase, nsteps;
    const float* W;
    float* Cout;
    if (GATHER) {
        b = blockIdx.x >> 2;
        tile = blockIdx.x & 3;
        W = blockIdx.y ? W1 : W0;
        kbase = blockIdx.z * (EE / NKV_SLICES);
        nsteps = (EE / NKV_SLICES) / 8;
        Cout = g_part + (size_t)(blockIdx.z * 2 + blockIdx.y) * (BB * KTOP * DD);
    } else {
        tile = blockIdx.x;
        W = W0;
        kbase = 0;
        nsteps = EE / 8;
        Cout = g_q;
    }

    const int a_row = tid & 127;
    const int a_kc = (tid >> 7) << 2;
    const int b_kr = tid >> 5;
    const int b_nc = (tid & 31) << 2;

    const float* aptr;
    if (GATHER) {
        int rl = tile * 128 + a_row;
        int rr = (rl < KTOP) ? g_topidx[b * KTOP + rl] : 0;
        aptr = A + ((size_t)b * TT + rr) * EE;
    } else {
        aptr = A + ((size_t)tile * 128 + a_row) * EE;
    }

    // preload first tile
    float4 av = *(const float4*)(aptr + kbase + a_kc);
    float4 bv = *(const float4*)(W + (size_t)(kbase + b_kr) * DD + b_nc);
    As[0][a_kc + 0][a_row] = av.x;
    As[0][a_kc + 1][a_row] = av.y;
    As[0][a_kc + 2][a_row] = av.z;
    As[0][a_kc + 3][a_row] = av.w;
    *(float4*)&Bs[0][b_kr][b_nc] = bv;
    __syncthreads();

    const int tx = tid & 15, ty = tid >> 4;
    unsigned long long acc[8][4];
#pragma unroll
    for (int i = 0; i < 8; i++)
#pragma unroll
        for (int p = 0; p < 4; p++) acc[i][p] = 0ull;

    int cur = 0;
    for (int it = 0; it < nsteps; ++it) {
        if (it + 1 < nsteps) {
            int ke = kbase + (it + 1) * 8;
            av = *(const float4*)(aptr + ke + a_kc);
            bv = *(const float4*)(W + (size_t)(ke + b_kr) * DD + b_nc);
        }
#pragma unroll
        for (int k = 0; k < 8; k++) {
            float4 a0 = *(const float4*)&As[cur][k][ty * 8];
            float4 a1 = *(const float4*)&As[cur][k][ty * 8 + 4];
            unsigned long long bp0 = *(const unsigned long long*)&Bs[cur][k][tx * 8];
            unsigned long long bp1 = *(const unsigned long long*)&Bs[cur][k][tx * 8 + 2];
            unsigned long long bp2 = *(const unsigned long long*)&Bs[cur][k][tx * 8 + 4];
            unsigned long long bp3 = *(const unsigned long long*)&Bs[cur][k][tx * 8 + 6];
            float aa[8] = {a0.x, a0.y, a0.z, a0.w, a1.x, a1.y, a1.z, a1.w};
#pragma unroll
            for (int i = 0; i < 8; i++) {
                unsigned long long ad = dup2(aa[i]);
                fma2(acc[i][0], ad, bp0);
                fma2(acc[i][1], ad, bp1);
                fma2(acc[i][2], ad, bp2);
                fma2(acc[i][3], ad, bp3);
            }
        }
        if (it + 1 < nsteps) {
            As[cur ^ 1][a_kc + 0][a_row] = av.x;
            As[cur ^ 1][a_kc + 1][a_row] = av.y;
            As[cur ^ 1][a_kc + 2][a_row] = av.z;
            As[cur ^ 1][a_kc + 3][a_row] = av.w;
            *(float4*)&Bs[cur ^ 1][b_kr][b_nc] = bv;
            __syncthreads();
            cur ^= 1;
        }
    }

    // epilogue
#pragma unroll
    for (int i = 0; i < 8; i++) {
        float2 f0 = unpk(acc[i][0]);
        float2 f1 = unpk(acc[i][1]);
        float2 f2 = unpk(acc[i][2]);
        float2 f3 = unpk(acc[i][3]);
        if (!GATHER) {
            int row = tile * 128 + ty * 8 + i;
            float* cp = Cout + (size_t)row * DD + tx * 8;
            *(float4*)cp = make_float4(f0.x, f0.y, f1.x, f1.y);
            *(float4*)(cp + 4) = make_float4(f2.x, f2.y, f3.x, f3.y);
            float sq = f0.x * f0.x + f0.y * f0.y + f1.x * f1.x + f1.y * f1.y +
                       f2.x * f2.x + f2.y * f2.y + f3.x * f3.x + f3.y * f3.y;
#pragma unroll
            for (int o = 8; o; o >>= 1) sq += __shfl_xor_sync(0xffffffffu, sq, o);
            if (tx == 0) g_norm[row] = sq;
        } else {
            int rl = tile * 128 + ty * 8 + i;
            if (rl < KTOP) {
                float* cp = Cout + ((size_t)b * KTOP + rl) * DD + tx * 8;
                *(float4*)cp = make_float4(f0.x, f0.y, f1.x, f1.y);
                *(float4*)(cp + 4) = make_float4(f2.x, f2.y, f3.x, f3.y);
            }
        }
    }
}

// ---------------- split-K reduction for k/v ----------------
__global__ void reduce_kv() {
    const int n = BB * KTOP * DD;
    for (int idx = blockIdx.x * blockDim.x + threadIdx.x; idx < 2 * n;
         idx += gridDim.x * blockDim.x) {
        int mat = (idx >= n) ? 1 : 0;
        int off = mat ? idx - n : idx;
        float s = 0.f;
#pragma unroll
        for (int z = 0; z < NKV_SLICES; z++)
            s += g_part[(size_t)(z * 2 + mat) * n + off];
        (mat ? g_vtop : g_ktop)[off] = s;
    }
}

// ---------------- per-batch exact top-k (bitonic sort, tie-break = lower index) ----
__global__ __launch_bounds__(1024) void topk_kernel() {
    __shared__ unsigned long long key[TT];
    __shared__ int sidx[KTOP];
    const int b = blockIdx.x, tid = threadIdx.x;
    for (int t = tid; t < TT; t += 1024) {
        unsigned bits = __float_as_uint(g_norm[b * TT + t]);  // >=0 -> monotonic bits
        key[t] = ((unsigned long long)bits << 32) | (unsigned)(0xFFFFFFFFu - t);
    }
    __syncthreads();
    for (int k = 2; k <= TT; k <<= 1) {
        for (int j = k >> 1; j > 0; j >>= 1) {
            for (int t = tid; t < TT; t += 1024) {
                int l = t ^ j;
                if (l > t) {
                    unsigned long long a = key[t], c = key[l];
                    bool up = ((t & k) == 0);
                    if ((a > c) == up) {
                        key[t] = c;
                        key[l] = a;
                    }
                }
            }
            __syncthreads();
        }
    }
    if (tid < KTOP) {
        unsigned long long kk = key[TT - 1 - tid];
        int idx = (int)(0xFFFFFFFFu - (unsigned)(kk & 0xFFFFFFFFull));
        g_topidx[b * KTOP + tid] = idx;
        sidx[tid] = idx;
    }
    __syncthreads();
    for (int u = tid; u < KTOP * DD; u += 1024) {
        int r = u >> 7, d = u & 127;
        g_qtop[((size_t)b * KTOP + r) * DD + d] =
            g_q[((size_t)b * TT + sidx[r]) * DD + d];
    }
}

// ---------------- attention on the top-k set, scattered store ----------------
__global__ __launch_bounds__(256) void attn_kernel(float* __restrict__ out) {
    constexpr int QT = 16;
    constexpr int NT = 26;   // 26*16 = 416 >= 409
    constexpr int CW = 416;
    __shared__ float q_s[QT][132];
    __shared__ float kv_s[QT][132];
    __shared__ float S_s[QT][CW];

    const int b = blockIdx.x / NT;
    const int qt = blockIdx.x % NT;
    const int q0 = qt * QT;
    const int tid = threadIdx.x;
    const float scale = 0.08838834764831845f;  // 1/sqrt(128)

    for (int u = tid; u < QT * DD; u += 256) {
        int i = u >> 7, d = u & 127;
        int r = q0 + i;
        q_s[i][d] = (r < KTOP) ? g_qtop[((size_t)b * KTOP + r) * DD + d] : 0.f;
    }

    const int i = tid >> 4;
    const int jj = tid & 15;

    // scores
    for (int jt = 0; jt < NT; jt++) {
        __syncthreads();
        for (int u = tid; u < QT * DD; u += 256) {
            int j2 = u >> 7, d = u & 127;
            int j = jt * QT + j2;
            kv_s[j2][d] = (j < KTOP) ? g_ktop[((size_t)b * KTOP + j) * DD + d] : 0.f;
        }
        __syncthreads();
        float s = 0.f;
#pragma unroll
        for (int d4 = 0; d4 < DD; d4 += 4) {
            float4 qa = *(const float4*)&q_s[i][d4];
            float4 kb = *(const float4*)&kv_s[jj][d4];
            s += qa.x * kb.x + qa.y * kb.y + qa.z * kb.z + qa.w * kb.w;
        }
        int j = jt * QT + jj;
        S_s[i][j] = (j < KTOP) ? s * scale : -1e30f;
    }
    __syncthreads();

    // softmax (row i handled by its 16-thread group)
    {
        int l = tid & 15;
        float m = -1e30f;
        for (int c = l; c < CW; c += 16) m = fmaxf(m, S_s[i][c]);
#pragma unroll
        for (int o = 8; o; o >>= 1) m = fmaxf(m, __shfl_xor_sync(0xffffffffu, m, o));
        float sum = 0.f;
        for (int c = l; c < CW; c += 16) {
            float e = __expf(S_s[i][c] - m);
            S_s[i][c] = e;
            sum += e;
        }
#pragma unroll
        for (int o = 8; o; o >>= 1) sum += __shfl_xor_sync(0xffffffffu, sum, o);
        float inv = 1.f / sum;
        for (int c = l; c < CW; c += 16) S_s[i][c] *= inv;
    }

    // P @ V
    float acc[8] = {0.f, 0.f, 0.f, 0.f, 0.f, 0.f, 0.f, 0.f};
    const int d0 = (tid & 15) * 8;
    for (int jt = 0; jt < NT; jt++) {
        __syncthreads();
        for (int u = tid; u < QT * DD; u += 256) {
            int j2 = u >> 7, d = u & 127;
            int j = jt * QT + j2;
            kv_s[j2][d] = (j < KTOP) ? g_vtop[((size_t)b * KTOP + j) * DD + d] : 0.f;
        }
        __syncthreads();
#pragma unroll
        for (int j2 = 0; j2 < QT; j2++) {
            float p = S_s[i][jt * QT + j2];
            float4 v0 = *(const float4*)&kv_s[j2][d0];
            float4 v1 = *(const float4*)&kv_s[j2][d0 + 4];
            acc[0] += p * v0.x;
            acc[1] += p * v0.y;
            acc[2] += p * v0.z;
            acc[3] += p * v0.w;
            acc[4] += p * v1.x;
            acc[5] += p * v1.y;
            acc[6] += p * v1.z;
            acc[7] += p * v1.w;
        }
    }
    int r = q0 + i;
    if (r < KTOP) {
        int rg = g_topidx[b * KTOP + r];
        float* op = out + ((size_t)b * TT + rg) * DD + d0;
        *(float4*)op = make_float4(acc[0], acc[1], acc[2], acc[3]);
        *(float4*)(op + 4) = make_float4(acc[4], acc[5], acc[6], acc[7]);
    }
}

// ---------------- launch ----------------
extern "C" void kernel_launch(void* const* d_in, const int* in_sizes, int n_in,
                              void* d_out, int out_size) {
    (void)in_sizes;
    (void)n_in;
    (void)out_size;
    const float* index = (const float*)d_in[0];
    const float* Wq = (const float*)d_in[1];
    const float* Wk = (const float*)d_in[2];
    const float* Wv = (const float*)d_in[3];
    float* out = (float*)d_out;

    zero_kernel<<<512, 256>>>((float4*)out, BB * TT * DD / 4);
    sgemm128<false><<<(BB * TT) / 128, 256>>>(index, Wq, nullptr);
    topk_kernel<<<BB, 1024>>>();
    sgemm128<true><<<dim3(16, 2, NKV_SLICES), 256>>>(index, Wk, Wv);
    reduce_kv<<<512, 256>>>();
    attn_kernel<<<BB * 26, 256>>>(out);
}